// round 11
// baseline (speedup 1.0000x reference)
#include <cuda_runtime.h>
#include <cuda_bf16.h>
#include <cstdint>

// Per-block partial sums + completion counter (no allocation allowed).
#define MAX_BLOCKS 2048
__device__ double g_partial_c[MAX_BLOCKS];
__device__ double g_partial_r[MAX_BLOCKS];
__device__ unsigned int g_done = 0;   // zero at module load; last block resets it

#define TILE_R 512        // rows per tile (multiple of 4 -> all copy sizes %16==0)
#define NSTAGES 2

struct Stage {
    int    cls[TILE_R];     // 2 KB
    float2 cout[TILE_R];    // 4 KB
    float4 rout[TILE_R];    // 8 KB
    float4 regt[TILE_R];    // 8 KB
};                          // 22 KB per stage

struct SmemLayout {
    unsigned long long bar[NSTAGES];
    double s_c[8], s_r[8];
    int    s_last;
    Stage  stage[NSTAGES] __align__(16);
};                          // ~44.2 KB static

__device__ __forceinline__ uint32_t smem_u32(const void* p) {
    uint32_t a;
    asm("{ .reg .u64 t; cvta.to.shared.u64 t, %1; cvt.u32.u64 %0, t; }" : "=r"(a) : "l"(p));
    return a;
}

__device__ __forceinline__ void mbar_init(uint32_t bar, uint32_t cnt) {
    asm volatile("mbarrier.init.shared.b64 [%0], %1;" :: "r"(bar), "r"(cnt) : "memory");
}
__device__ __forceinline__ void mbar_expect_tx(uint32_t bar, uint32_t bytes) {
    asm volatile("mbarrier.arrive.expect_tx.shared.b64 _, [%0], %1;" :: "r"(bar), "r"(bytes) : "memory");
}
__device__ __forceinline__ void mbar_wait(uint32_t bar, uint32_t parity) {
    asm volatile(
        "{\n\t"
        ".reg .pred P;\n\t"
        "WAIT_%=:\n\t"
        "mbarrier.try_wait.parity.acquire.cta.shared::cta.b64 P, [%0], %1, 0x989680;\n\t"
        "@P bra.uni DONE_%=;\n\t"
        "bra.uni WAIT_%=;\n\t"
        "DONE_%=:\n\t"
        "}" :: "r"(bar), "r"(parity) : "memory");
}
__device__ __forceinline__ void bulk_cp(uint32_t dst_smem, const void* src_gmem,
                                        uint32_t bytes, uint32_t bar) {
    asm volatile(
        "cp.async.bulk.shared::cta.global.mbarrier::complete_tx::bytes [%0], [%1], %2, [%3];"
        :: "r"(dst_smem), "l"(src_gmem), "r"(bytes), "r"(bar) : "memory");
}

__device__ __forceinline__ float smooth_l1(float d) {
    float ad = fabsf(d);
    return (ad < 1.0f) ? 0.5f * d * d : ad - 0.5f;
}

// CE(lbl=0)=softplus(cy-cx), CE(lbl=1)=softplus(cx-cy); softplus(u)=max(u,0)+log1p(e^-|u|)
__device__ __forceinline__ void row_work(int lbl, float cx, float cy,
                                         const float4& r, const float4& t,
                                         float& c_acc, float& r_acc) {
    float d  = cx - cy;
    float u  = (lbl == 1) ? d : -d;
    float sp = fmaxf(u, 0.0f) + log1pf(__expf(-fabsf(d)));
    c_acc += (lbl <= 1) ? sp : 0.0f;

    float s = smooth_l1(r.x - t.x) + smooth_l1(r.y - t.y)
            + smooth_l1(r.z - t.z) + smooth_l1(r.w - t.w);
    r_acc += (lbl == 1) ? (s * 0.25f) : 0.0f;
}

__global__ void __launch_bounds__(256)
mbl_pipe_kernel(const float2* __restrict__ g_cout,
                const float4* __restrict__ g_rout,
                const int*    __restrict__ g_cls,
                const float4* __restrict__ g_reg,
                int n,
                float* __restrict__ out) {
    __shared__ SmemLayout sm;
    int tid = threadIdx.x;

    uint32_t bar0 = smem_u32(&sm.bar[0]);
    if (tid == 0) {
        mbar_init(bar0,     1);
        mbar_init(bar0 + 8, 1);
    }
    __syncthreads();

    int n_main  = n & ~3;                       // multiple of 4 rows via bulk copies
    int n_tiles = (n_main + TILE_R - 1) / TILE_R;

    float c_acc = 0.0f;
    float r_acc = 0.0f;

    uint32_t st_u32[NSTAGES];
    st_u32[0] = smem_u32(&sm.stage[0]);
    st_u32[1] = smem_u32(&sm.stage[1]);

    // producer: issue tile t into stage s (thread 0 only)
    auto issue = [&](int t, int s) {
        int row0 = t * TILE_R;
        int rows = min(TILE_R, n_main - row0);
        uint32_t bar = bar0 + 8u * s;
        uint32_t b_cls  = rows * 4u;
        uint32_t b_cout = rows * 8u;
        uint32_t b_r    = rows * 16u;
        mbar_expect_tx(bar, b_cls + b_cout + 2u * b_r);
        uint32_t base = st_u32[s];
        bulk_cp(base + (uint32_t)offsetof(Stage, cls),  g_cls  + row0, b_cls,  bar);
        bulk_cp(base + (uint32_t)offsetof(Stage, cout), g_cout + row0, b_cout, bar);
        bulk_cp(base + (uint32_t)offsetof(Stage, rout), g_rout + row0, b_r,    bar);
        bulk_cp(base + (uint32_t)offsetof(Stage, regt), g_reg  + row0, b_r,    bar);
    };

    // prologue: prime stage 0 with this CTA's first tile
    int t0 = blockIdx.x;
    if (t0 < n_tiles && tid == 0) issue(t0, 0);

    int i = 0;
    for (int t = t0; t < n_tiles; t += gridDim.x, i++) {
        int s = i & 1;
        // prefetch next tile into the other stage (free: consumed >=1 iter ago)
        int tn = t + gridDim.x;
        if (tn < n_tiles && tid == 0) issue(tn, s ^ 1);

        mbar_wait(bar0 + 8u * s, (i >> 1) & 1);

        int rows = min(TILE_R, n_main - t * TILE_R);
        const Stage& S = sm.stage[s];
        #pragma unroll
        for (int rr = tid; rr < TILE_R; rr += 256) {
            if (rr < rows) {
                int    lbl = S.cls[rr];
                float2 c   = S.cout[rr];
                float4 rv  = S.rout[rr];
                float4 tv  = S.regt[rr];
                row_work(lbl, c.x, c.y, rv, tv, c_acc, r_acc);
            }
        }
        __syncthreads();   // stage s free for re-issue
    }

    // leftover rows (n % 4), direct global loads by block 0 thread 0
    if (blockIdx.x == 0 && tid == 0) {
        for (int r0 = n_main; r0 < n; r0++) {
            int    lbl = g_cls[r0];
            float2 c   = g_cout[r0];
            float4 rv  = g_rout[r0];
            float4 tv  = g_reg[r0];
            row_work(lbl, c.x, c.y, rv, tv, c_acc, r_acc);
        }
    }

    // ---- block reduction ----
    #pragma unroll
    for (int off = 16; off > 0; off >>= 1) {
        c_acc += __shfl_down_sync(0xFFFFFFFFu, c_acc, off);
        r_acc += __shfl_down_sync(0xFFFFFFFFu, r_acc, off);
    }
    int lane = tid & 31;
    int wid  = tid >> 5;
    if (lane == 0) { sm.s_c[wid] = (double)c_acc; sm.s_r[wid] = (double)r_acc; }
    __syncthreads();

    if (tid == 0) {
        double cc = 0.0, rr = 0.0;
        #pragma unroll
        for (int w = 0; w < 8; w++) { cc += sm.s_c[w]; rr += sm.s_r[w]; }
        g_partial_c[blockIdx.x] = cc;
        g_partial_r[blockIdx.x] = rr;
        __threadfence();
        unsigned int tk = atomicAdd(&g_done, 1u);
        sm.s_last = (tk == gridDim.x - 1) ? 1 : 0;
    }
    __syncthreads();

    // ---- last block: reduce per-block partials and finalize ----
    if (sm.s_last) {
        __threadfence();
        double cc = 0.0, rr = 0.0;
        for (int b = tid; b < gridDim.x; b += blockDim.x) {
            cc += g_partial_c[b];
            rr += g_partial_r[b];
        }
        #pragma unroll
        for (int off = 16; off > 0; off >>= 1) {
            cc += __shfl_down_sync(0xFFFFFFFFu, cc, off);
            rr += __shfl_down_sync(0xFFFFFFFFu, rr, off);
        }
        if (lane == 0) { sm.s_c[wid] = cc; sm.s_r[wid] = rr; }
        __syncthreads();
        if (tid == 0) {
            double fc = 0.0, fr = 0.0;
            #pragma unroll
            for (int w = 0; w < 8; w++) { fc += sm.s_c[w]; fr += sm.s_r[w]; }
            double closs = fc / 64.0;
            double rloss = fr / 16.0;
            out[0] = (float)closs;
            out[1] = (float)rloss;
            out[2] = (float)(closs + 10.0 * rloss);
            g_done = 0;   // reset for next graph replay
        }
    }
}

extern "C" void kernel_launch(void* const* d_in, const int* in_sizes, int n_in,
                              void* d_out, int out_size) {
    const float2* cout  = (const float2*)d_in[0];   // [N,2] f32
    const float4* rout  = (const float4*)d_in[1];   // [N,4] f32
    const int*    cls_t = (const int*)d_in[2];      // [N] int32
    const float4* reg_t = (const float4*)d_in[3];   // [N,4] f32
    float* out = (float*)d_out;

    int n = in_sizes[2];

    int n_tiles = ((n & ~3) + TILE_R - 1) / TILE_R;
    int blocks = 592;                 // 148 SMs * 4 CTAs (45 KB smem -> 5 CTAs/SM max)
    if (blocks > n_tiles) blocks = n_tiles;
    if (blocks < 1) blocks = 1;
    if (blocks > MAX_BLOCKS) blocks = MAX_BLOCKS;

    mbl_pipe_kernel<<<blocks, 256>>>(cout, rout, cls_t, reg_t, n, out);
}